// round 2
// baseline (speedup 1.0000x reference)
#include <cuda_runtime.h>

#define B_    2
#define QLEN  2048
#define HID   2048
#define NH    16
#define NKV   4
#define HD    128

// Scratch (device globals are the sanctioned scratch mechanism)
__device__ float g_q [(size_t)B_ * NH * QLEN * HD];   // (b,h,q,d) 32MB
__device__ float g_ao[(size_t)B_ * QLEN * NH * HD];   // (b,q,h,d) 32MB

typedef unsigned long long ull;

__device__ __forceinline__ ull pack2(float x, float y) {
    ull r; asm("mov.b64 %0, {%1,%2};" : "=l"(r) : "f"(x), "f"(y)); return r;
}
__device__ __forceinline__ void unpack2(ull v, float &x, float &y) {
    asm("mov.b64 {%0,%1}, %2;" : "=f"(x), "=f"(y) : "l"(v));
}
__device__ __forceinline__ void fma2(ull &d, ull a, ull b) {
    asm("fma.rn.f32x2 %0, %1, %2, %3;" : "=l"(d) : "l"(a), "l"(b), "l"(d));
}
__device__ __forceinline__ void mul2(ull &d, ull a, ull b) {
    asm("mul.rn.f32x2 %0, %1, %2;" : "=l"(d) : "l"(a), "l"(b));
}

// ---------------------------------------------------------------------------
// 128x128x8 SGEMM, 256 threads, 8x8 microtile as 8x4 packed f32x2.
// QMODE=1: scatter into g_q with (b,h,q,d) layout + bias. QMODE=0: row-major C.
// ---------------------------------------------------------------------------
template <int QMODE>
__global__ void __launch_bounds__(256, 2)
sgemm128(const float* __restrict__ A, const float* __restrict__ Bm,
         const float* __restrict__ bias, float* __restrict__ C,
         int M, int N, int K)
{
    __shared__ float As[8][128];   // transposed: As[k][m]
    __shared__ float Bs[8][128];

    int tid = threadIdx.x;
    int tx = tid & 15, ty = tid >> 4;
    int bx = blockIdx.x, by = blockIdx.y;

    ull acc[8][4];
#pragma unroll
    for (int i = 0; i < 8; i++)
#pragma unroll
        for (int j = 0; j < 4; j++) acc[i][j] = 0ULL;

    int ar = tid >> 1, ac = (tid & 1) * 4;       // A tile loader coords
    int br = tid >> 5, bc = (tid & 31) * 4;      // B tile loader coords
    const float* Ap = A + (size_t)(by * 128 + ar) * K + ac;
    const float* Bp = Bm + (size_t)br * N + bx * 128 + bc;

    float4 av = *(const float4*)(Ap);
    float4 bv = *(const float4*)(Bp);

    for (int kt = 0; kt < K; kt += 8) {
        __syncthreads();
        As[ac + 0][ar] = av.x; As[ac + 1][ar] = av.y;
        As[ac + 2][ar] = av.z; As[ac + 3][ar] = av.w;
        *(float4*)&Bs[br][bc] = bv;
        __syncthreads();
        if (kt + 8 < K) {
            av = *(const float4*)(Ap + kt + 8);
            bv = *(const float4*)(Bp + (size_t)(kt + 8) * N);
        }
#pragma unroll
        for (int k = 0; k < 8; k++) {
            ulonglong2 b01 = *(const ulonglong2*)&Bs[k][tx * 8];
            ulonglong2 b23 = *(const ulonglong2*)&Bs[k][tx * 8 + 4];
            float4 a0 = *(const float4*)&As[k][ty * 8];
            float4 a1 = *(const float4*)&As[k][ty * 8 + 4];
            float af[8] = {a0.x, a0.y, a0.z, a0.w, a1.x, a1.y, a1.z, a1.w};
#pragma unroll
            for (int i = 0; i < 8; i++) {
                ull aa = pack2(af[i], af[i]);
                fma2(acc[i][0], aa, b01.x);
                fma2(acc[i][1], aa, b01.y);
                fma2(acc[i][2], aa, b23.x);
                fma2(acc[i][3], aa, b23.y);
            }
        }
    }

#pragma unroll
    for (int i = 0; i < 8; i++) {
        int row = by * 128 + ty * 8 + i;
#pragma unroll
        for (int jp = 0; jp < 4; jp++) {
            float x, y; unpack2(acc[i][jp], x, y);
            int c0 = bx * 128 + tx * 8 + jp * 2;
            if (bias) { x += bias[c0]; y += bias[c0 + 1]; }
            if (QMODE) {
                int b = row >> 11, q = row & (QLEN - 1);
                int h = c0 >> 7, d = c0 & (HD - 1);
                float2* o = (float2*)&g_q[(((size_t)(b * NH + h)) * QLEN + q) * HD + d];
                *o = make_float2(x, y);
            } else {
                *(float2*)&C[(size_t)row * N + c0] = make_float2(x, y);
            }
        }
    }
}

// ---------------------------------------------------------------------------
// RoPE in-place on g_q. One thread per (b,h,q,d<64) pair.
// ---------------------------------------------------------------------------
__global__ void rope_kernel(const float* __restrict__ cosp, const float* __restrict__ sinp)
{
    int t = blockIdx.x * blockDim.x + threadIdx.x;
    int d = t & 63;
    int q = (t >> 6) & (QLEN - 1);
    int bh = t >> 17;
    int b = bh >> 4;
    size_t base  = ((size_t)bh * QLEN + q) * HD;
    size_t cbase = ((size_t)b * QLEN + q) * HD;
    float x1 = g_q[base + d], x2 = g_q[base + d + 64];
    float c1 = cosp[cbase + d],      s1 = sinp[cbase + d];
    float c2 = cosp[cbase + d + 64], s2 = sinp[cbase + d + 64];
    g_q[base + d]      = x1 * c1 - x2 * s1;
    g_q[base + d + 64] = x2 * c2 + x1 * s2;
}

// ---------------------------------------------------------------------------
// Glide attention: 64-query tile per CTA, 64-key tiles, online softmax.
// K is staged transposed+XOR-swizzled (Kt[d][j], col4 = g ^ (d&15)) so the
// S-phase LDS.128 k-loads are bank-conflict free.
// Heavy CTAs (large qi) are launched FIRST (LPT scheduling) to cut the tail.
// ---------------------------------------------------------------------------
#define ATT_SMEM_FLOATS (64*132 + 128*64 + 64*128 + 64*68)

__global__ void __launch_bounds__(256, 1)
attn_kernel(const float* __restrict__ Kc, const float* __restrict__ Vc)
{
    extern __shared__ float sm[];
    float* Qs = sm;                    // [64][132]  (pad breaks bank conflicts)
    float* Kt = Qs + 64 * 132;         // [128][64]  transposed + swizzled
    float* Vs = Kt + 128 * 64;         // [64][128]
    float* Ps = Vs + 64 * 128;         // [64][68]

    const float SCALE = 0.08838834764831843f;  // 128^-0.5

    int tid = threadIdx.x;
    int tx = tid & 15, ty = tid >> 4;
    int qi = (gridDim.x - 1) - blockIdx.x;   // heavy tiles first
    int h = blockIdx.y, b = blockIdx.z;
    int q0 = qi * 64;
    int kvh = h >> 2;                  // groups = 4
    int qy = ty * 4;

    // load Q tile (already RoPE'd)
    {
        const float* qg = &g_q[(((size_t)(b * NH + h)) * QLEN + q0) * HD];
        for (int i = tid; i < 64 * 32; i += 256) {
            int r = i >> 5, d4 = (i & 31) << 2;
            *(float4*)&Qs[r * 132 + d4] = *(const float4*)&qg[r * HD + d4];
        }
    }

    ull acco[4][4];
#pragma unroll
    for (int i = 0; i < 4; i++)
#pragma unroll
        for (int j = 0; j < 4; j++) acco[i][j] = 0ULL;
    float m_run[4] = {-1e30f, -1e30f, -1e30f, -1e30f};
    float l_run[4] = {0.f, 0.f, 0.f, 0.f};

    int ntiles = qi + 1;

    for (int t = 0; t < ntiles; t++) {
        int k0 = t * 64;
        bool masked = (t == ntiles - 1);
        __syncthreads();   // protect Kt/Vs/Ps from previous tile's readers

        // K tile: transpose into Kt[d][j] with XOR swizzle on the j-group
        {
            int d = tid & 127, g2 = tid >> 7;
#pragma unroll
            for (int p = 0; p < 8; p++) {
                int jg = p * 2 + g2;
                const float* kg = &Kc[(((size_t)(b * QLEN) + k0 + jg * 4) * NKV + kvh) * HD + d];
                float r0 = kg[0];
                float r1 = kg[(size_t)NKV * HD];
                float r2 = kg[(size_t)2 * NKV * HD];
                float r3 = kg[(size_t)3 * NKV * HD];
                int pc = jg ^ (d & 15);
                *(float4*)&Kt[d * 64 + pc * 4] = make_float4(r0, r1, r2, r3);
            }
        }
        // V tile, row-major
        for (int i = tid; i < 64 * 32; i += 256) {
            int r = i >> 5, d4 = (i & 31) << 2;
            *(float4*)&Vs[r * 128 + d4] =
                *(const float4*)&Vc[(((size_t)(b * QLEN) + k0 + r) * NKV + kvh) * HD + d4];
        }
        __syncthreads();

        // ---- S = Q K^T (4q x 4k per thread, packed pairs) ----
        ull accs[4][2];
#pragma unroll
        for (int i = 0; i < 4; i++) { accs[i][0] = 0ULL; accs[i][1] = 0ULL; }
#pragma unroll 4
        for (int d = 0; d < 128; d++) {
            ulonglong2 kk = *(const ulonglong2*)&Kt[d * 64 + ((tx ^ (d & 15)) << 2)];
#pragma unroll
            for (int i = 0; i < 4; i++) {
                float qv = Qs[(qy + i) * 132 + d];
                ull qq = pack2(qv, qv);
                fma2(accs[i][0], qq, kk.x);
                fma2(accs[i][1], qq, kk.y);
            }
        }

        // ---- online softmax ----
        float alpha[4];
#pragma unroll
        for (int i = 0; i < 4; i++) {
            float s0, s1, s2, s3;
            unpack2(accs[i][0], s0, s1);
            unpack2(accs[i][1], s2, s3);
            s0 *= SCALE; s1 *= SCALE; s2 *= SCALE; s3 *= SCALE;
            if (masked) {
                int iq = q0 + qy + i;
                int kend = (iq < 4) ? 4 : (iq & ~3);
                int kb = k0 + tx * 4;
                if (kb + 0 >= kend) s0 = -1e30f;
                if (kb + 1 >= kend) s1 = -1e30f;
                if (kb + 2 >= kend) s2 = -1e30f;
                if (kb + 3 >= kend) s3 = -1e30f;
            }
            float mt = fmaxf(fmaxf(s0, s1), fmaxf(s2, s3));
#pragma unroll
            for (int o = 8; o > 0; o >>= 1) mt = fmaxf(mt, __shfl_xor_sync(0xffffffffu, mt, o));
            float mn = fmaxf(m_run[i], mt);
            float al = __expf(m_run[i] - mn);
            m_run[i] = mn;
            float p0 = __expf(s0 - mn), p1 = __expf(s1 - mn);
            float p2 = __expf(s2 - mn), p3 = __expf(s3 - mn);
            float rs = p0 + p1 + p2 + p3;
#pragma unroll
            for (int o = 8; o > 0; o >>= 1) rs += __shfl_xor_sync(0xffffffffu, rs, o);
            l_run[i] = l_run[i] * al + rs;
            alpha[i] = al;
            *(float4*)&Ps[(qy + i) * 68 + tx * 4] = make_float4(p0, p1, p2, p3);
        }
        // rescale running O
#pragma unroll
        for (int i = 0; i < 4; i++) {
            ull a2 = pack2(alpha[i], alpha[i]);
#pragma unroll
            for (int jp = 0; jp < 4; jp++) mul2(acco[i][jp], acco[i][jp], a2);
        }
        __syncthreads();   // Ps visible to all

        // ---- O += P V (4q x 8d per thread, packed pairs) ----
#pragma unroll 4
        for (int k = 0; k < 64; k++) {
            ulonglong2 v0 = *(const ulonglong2*)&Vs[k * 128 + tx * 8];
            ulonglong2 v1 = *(const ulonglong2*)&Vs[k * 128 + tx * 8 + 4];
#pragma unroll
            for (int i = 0; i < 4; i++) {
                float pv = Ps[(qy + i) * 68 + k];
                ull pp = pack2(pv, pv);
                fma2(acco[i][0], pp, v0.x);
                fma2(acco[i][1], pp, v0.y);
                fma2(acco[i][2], pp, v1.x);
                fma2(acco[i][3], pp, v1.y);
            }
        }
    }

    // normalize + store to (b,q,h,d)
#pragma unroll
    for (int i = 0; i < 4; i++) {
        float inv = 1.0f / l_run[i];
        float o[8];
        unpack2(acco[i][0], o[0], o[1]);
        unpack2(acco[i][1], o[2], o[3]);
        unpack2(acco[i][2], o[4], o[5]);
        unpack2(acco[i][3], o[6], o[7]);
        size_t base = (((size_t)b * QLEN + q0 + qy + i) * NH + h) * HD + tx * 8;
        *(float4*)&g_ao[base]     = make_float4(o[0]*inv, o[1]*inv, o[2]*inv, o[3]*inv);
        *(float4*)&g_ao[base + 4] = make_float4(o[4]*inv, o[5]*inv, o[6]*inv, o[7]*inv);
    }
}

// ---------------------------------------------------------------------------
extern "C" void kernel_launch(void* const* d_in, const int* in_sizes, int n_in,
                              void* d_out, int out_size)
{
    const float* X    = (const float*)d_in[0];
    const float* Kc   = (const float*)d_in[1];
    const float* Vc   = (const float*)d_in[2];
    const float* cosp = (const float*)d_in[3];
    const float* sinp = (const float*)d_in[4];
    const float* Wq   = (const float*)d_in[5];
    const float* bq   = (const float*)d_in[6];
    const float* Wo   = (const float*)d_in[7];
    float* out = (float*)d_out;

    void* gaop;
    cudaGetSymbolAddress(&gaop, g_ao);

    // 1) Q projection + bias, scattered to (b,h,q,d)
    sgemm128<1><<<dim3(HID / 128, (B_ * QLEN) / 128), 256>>>(
        X, Wq, bq, nullptr, B_ * QLEN, NH * HD, HID);

    // 2) RoPE in place
    rope_kernel<<<(B_ * NH * QLEN * 64) / 256, 256>>>(cosp, sinp);

    // 3) glide attention
    size_t smem = (size_t)ATT_SMEM_FLOATS * sizeof(float);
    cudaFuncSetAttribute(attn_kernel, cudaFuncAttributeMaxDynamicSharedMemorySize, (int)smem);
    attn_kernel<<<dim3(QLEN / 64, NH, B_), 256, smem>>>(Kc, Vc);

    // 4) output projection
    sgemm128<0><<<dim3(HID / 128, (B_ * QLEN) / 128), 256>>>(
        (const float*)gaop, Wo, nullptr, out, B_ * QLEN, HID, NH * HD);
}

// round 4
// speedup vs baseline: 1.3974x; 1.3974x over previous
#include <cuda_runtime.h>

#define B_    2
#define QLEN  2048
#define HID   2048
#define NH    16
#define NKV   4
#define HD    128
#define BK    16

// Scratch (device globals are the sanctioned scratch mechanism)
__device__ float g_q [(size_t)B_ * NH * QLEN * HD];   // (b,h,q,d) 32MB
__device__ float g_ao[(size_t)B_ * QLEN * NH * HD];   // (b,q,h,d) 32MB

typedef unsigned long long ull;

__device__ __forceinline__ ull pack2(float x, float y) {
    ull r; asm("mov.b64 %0, {%1,%2};" : "=l"(r) : "f"(x), "f"(y)); return r;
}
__device__ __forceinline__ void unpack2(ull v, float &x, float &y) {
    asm("mov.b64 {%0,%1}, %2;" : "=f"(x), "=f"(y) : "l"(v));
}
__device__ __forceinline__ void fma2(ull &d, ull a, ull b) {
    asm("fma.rn.f32x2 %0, %1, %2, %3;" : "=l"(d) : "l"(a), "l"(b), "l"(d));
}
__device__ __forceinline__ void mul2(ull &d, ull a, ull b) {
    asm("mul.rn.f32x2 %0, %1, %2;" : "=l"(d) : "l"(a), "l"(b));
}

// tf32 round-to-nearest (unbiased; applied once at SMEM-store time)
__device__ __forceinline__ float tf32r(float x) {
    unsigned u; asm("cvt.rna.tf32.f32 %0, %1;" : "=r"(u) : "f"(x));
    return __uint_as_float(u);
}

__device__ __forceinline__ void mma_tf32(float* c, const unsigned* a, const unsigned* b) {
    asm("mma.sync.aligned.m16n8k8.row.col.f32.tf32.tf32.f32 "
        "{%0,%1,%2,%3}, {%4,%5,%6,%7}, {%8,%9}, {%0,%1,%2,%3};"
        : "+f"(c[0]), "+f"(c[1]), "+f"(c[2]), "+f"(c[3])
        : "r"(a[0]), "r"(a[1]), "r"(a[2]), "r"(a[3]), "r"(b[0]), "r"(b[1]));
}

// ---------------------------------------------------------------------------
// 128x128 tf32 tensor-core GEMM. 8 warps (2x4), warp tile 64x32 = 4x4 atoms
// of m16n8k8. BK=16, double-buffered SMEM, ONE syncthreads per k-step.
// QMODE=1: scatter into g_q as (b,h,q,d) + bias. QMODE=0: row-major C.
// ---------------------------------------------------------------------------
template <int QMODE>
__global__ void __launch_bounds__(256, 2)
tgemm128(const float* __restrict__ A, const float* __restrict__ Bm,
         const float* __restrict__ bias, float* __restrict__ C,
         int M, int N, int K)
{
    __shared__ float As[2][BK][132];   // [k][m], tf32-rounded
    __shared__ float Bs[2][BK][132];   // [k][n], tf32-rounded

    int tid = threadIdx.x;
    int w = tid >> 5, l = tid & 31;
    int wr = w >> 2, wc = w & 3;          // warp grid 2x4
    int gid = l >> 2, tg = l & 3;
    int bx = blockIdx.x, by = blockIdx.y;

    float c[4][4][4];
#pragma unroll
    for (int i = 0; i < 4; i++)
#pragma unroll
        for (int j = 0; j < 4; j++)
#pragma unroll
            for (int r = 0; r < 4; r++) c[i][j][r] = 0.f;

    int am = tid >> 1, ak = (tid & 1) * 8;   // A loader: 128 rows x 16 k
    int bk = tid >> 4, bn = (tid & 15) * 8;  // B loader: 16 k x 128 n
    const float* Ap = A + (size_t)(by * 128 + am) * K + ak;
    const float* Bp = Bm + (size_t)bk * N + bx * 128 + bn;

    float4 av0 = *(const float4*)(Ap);
    float4 av1 = *(const float4*)(Ap + 4);
    float4 bv0 = *(const float4*)(Bp);
    float4 bv1 = *(const float4*)(Bp + 4);

    // prologue store, buffer 0
    {
        As[0][ak+0][am] = tf32r(av0.x); As[0][ak+1][am] = tf32r(av0.y);
        As[0][ak+2][am] = tf32r(av0.z); As[0][ak+3][am] = tf32r(av0.w);
        As[0][ak+4][am] = tf32r(av1.x); As[0][ak+5][am] = tf32r(av1.y);
        As[0][ak+6][am] = tf32r(av1.z); As[0][ak+7][am] = tf32r(av1.w);
        float4 t0 = make_float4(tf32r(bv0.x), tf32r(bv0.y), tf32r(bv0.z), tf32r(bv0.w));
        float4 t1 = make_float4(tf32r(bv1.x), tf32r(bv1.y), tf32r(bv1.z), tf32r(bv1.w));
        *(float4*)&Bs[0][bk][bn]     = t0;
        *(float4*)&Bs[0][bk][bn + 4] = t1;
    }
    __syncthreads();

    int p = 0;
    for (int kt = 0; kt < K; kt += BK) {
        bool more = (kt + BK) < K;
        if (more) {
            av0 = *(const float4*)(Ap + kt + BK);
            av1 = *(const float4*)(Ap + kt + BK + 4);
            bv0 = *(const float4*)(Bp + (size_t)(kt + BK) * N);
            bv1 = *(const float4*)(Bp + (size_t)(kt + BK) * N + 4);
        }
#pragma unroll
        for (int ka = 0; ka < 2; ka++) {
            int kb = ka * 8;
            unsigned bf[4][2];
#pragma unroll
            for (int nj = 0; nj < 4; nj++) {
                int nb = wc * 32 + nj * 8 + gid;
                bf[nj][0] = __float_as_uint(Bs[p][kb + tg    ][nb]);
                bf[nj][1] = __float_as_uint(Bs[p][kb + tg + 4][nb]);
            }
#pragma unroll
            for (int mi = 0; mi < 4; mi++) {
                int mb = wr * 64 + mi * 16;
                unsigned af[4];
                af[0] = __float_as_uint(As[p][kb + tg    ][mb + gid]);
                af[1] = __float_as_uint(As[p][kb + tg    ][mb + gid + 8]);
                af[2] = __float_as_uint(As[p][kb + tg + 4][mb + gid]);
                af[3] = __float_as_uint(As[p][kb + tg + 4][mb + gid + 8]);
#pragma unroll
                for (int nj = 0; nj < 4; nj++)
                    mma_tf32(c[mi][nj], af, bf[nj]);
            }
        }
        if (more) {
            int q = p ^ 1;
            As[q][ak+0][am] = tf32r(av0.x); As[q][ak+1][am] = tf32r(av0.y);
            As[q][ak+2][am] = tf32r(av0.z); As[q][ak+3][am] = tf32r(av0.w);
            As[q][ak+4][am] = tf32r(av1.x); As[q][ak+5][am] = tf32r(av1.y);
            As[q][ak+6][am] = tf32r(av1.z); As[q][ak+7][am] = tf32r(av1.w);
            float4 t0 = make_float4(tf32r(bv0.x), tf32r(bv0.y), tf32r(bv0.z), tf32r(bv0.w));
            float4 t1 = make_float4(tf32r(bv1.x), tf32r(bv1.y), tf32r(bv1.z), tf32r(bv1.w));
            *(float4*)&Bs[q][bk][bn]     = t0;
            *(float4*)&Bs[q][bk][bn + 4] = t1;
            __syncthreads();
            p = q;
        }
    }

    // epilogue
#pragma unroll
    for (int mi = 0; mi < 4; mi++) {
#pragma unroll
        for (int nj = 0; nj < 4; nj++) {
            int row0 = by * 128 + wr * 64 + mi * 16 + gid;
            int col0 = bx * 128 + wc * 32 + nj * 8 + tg * 2;
            float b0 = bias ? bias[col0] : 0.f;
            float b1 = bias ? bias[col0 + 1] : 0.f;
            float2 v0 = make_float2(c[mi][nj][0] + b0, c[mi][nj][1] + b1);
            float2 v1 = make_float2(c[mi][nj][2] + b0, c[mi][nj][3] + b1);
            if (QMODE) {
                int b  = row0 >> 11, q = row0 & (QLEN - 1);
                int h  = col0 >> 7,  d = col0 & (HD - 1);
                *(float2*)&g_q[(((size_t)(b * NH + h)) * QLEN + q) * HD + d] = v0;
                int rb = (row0 + 8) >> 11, rq = (row0 + 8) & (QLEN - 1);
                *(float2*)&g_q[(((size_t)(rb * NH + h)) * QLEN + rq) * HD + d] = v1;
            } else {
                *(float2*)&C[(size_t)row0 * N + col0]       = v0;
                *(float2*)&C[(size_t)(row0 + 8) * N + col0] = v1;
            }
        }
    }
}

// ---------------------------------------------------------------------------
// RoPE in-place on g_q. One thread per (b,h,q,d<64) pair.
// ---------------------------------------------------------------------------
__global__ void rope_kernel(const float* __restrict__ cosp, const float* __restrict__ sinp)
{
    int t = blockIdx.x * blockDim.x + threadIdx.x;
    int d = t & 63;
    int q = (t >> 6) & (QLEN - 1);
    int bh = t >> 17;
    int b = bh >> 4;
    size_t base  = ((size_t)bh * QLEN + q) * HD;
    size_t cbase = ((size_t)b * QLEN + q) * HD;
    float x1 = g_q[base + d], x2 = g_q[base + d + 64];
    float c1 = cosp[cbase + d],      s1 = sinp[cbase + d];
    float c2 = cosp[cbase + d + 64], s2 = sinp[cbase + d + 64];
    g_q[base + d]      = x1 * c1 - x2 * s1;
    g_q[base + d + 64] = x2 * c2 + x1 * s2;
}

// ---------------------------------------------------------------------------
// Glide attention: 64-query tile per CTA, 64-key tiles, online softmax.
// Heavy CTAs (large qi) launched first (LPT).
// ---------------------------------------------------------------------------
#define ATT_SMEM_FLOATS (64*132 + 128*64 + 64*128 + 64*68)

__global__ void __launch_bounds__(256, 1)
attn_kernel(const float* __restrict__ Kc, const float* __restrict__ Vc)
{
    extern __shared__ float sm[];
    float* Qs = sm;                    // [64][132]
    float* Kt = Qs + 64 * 132;         // [128][64]  transposed + swizzled
    float* Vs = Kt + 128 * 64;         // [64][128]
    float* Ps = Vs + 64 * 128;         // [64][68]

    const float SCALE = 0.08838834764831843f;  // 128^-0.5

    int tid = threadIdx.x;
    int tx = tid & 15, ty = tid >> 4;
    int qi = (gridDim.x - 1) - blockIdx.x;   // heavy tiles first
    int h = blockIdx.y, b = blockIdx.z;
    int q0 = qi * 64;
    int kvh = h >> 2;
    int qy = ty * 4;

    {
        const float* qg = &g_q[(((size_t)(b * NH + h)) * QLEN + q0) * HD];
        for (int i = tid; i < 64 * 32; i += 256) {
            int r = i >> 5, d4 = (i & 31) << 2;
            *(float4*)&Qs[r * 132 + d4] = *(const float4*)&qg[r * HD + d4];
        }
    }

    ull acco[4][4];
#pragma unroll
    for (int i = 0; i < 4; i++)
#pragma unroll
        for (int j = 0; j < 4; j++) acco[i][j] = 0ULL;
    float m_run[4] = {-1e30f, -1e30f, -1e30f, -1e30f};
    float l_run[4] = {0.f, 0.f, 0.f, 0.f};

    int ntiles = qi + 1;

    for (int t = 0; t < ntiles; t++) {
        int k0 = t * 64;
        bool masked = (t == ntiles - 1);
        __syncthreads();

        {
            int d = tid & 127, g2 = tid >> 7;
#pragma unroll
            for (int p = 0; p < 8; p++) {
                int jg = p * 2 + g2;
                const float* kg = &Kc[(((size_t)(b * QLEN) + k0 + jg * 4) * NKV + kvh) * HD + d];
                float r0 = kg[0];
                float r1 = kg[(size_t)NKV * HD];
                float r2 = kg[(size_t)2 * NKV * HD];
                float r3 = kg[(size_t)3 * NKV * HD];
                int pc = jg ^ (d & 15);
                *(float4*)&Kt[d * 64 + pc * 4] = make_float4(r0, r1, r2, r3);
            }
        }
        for (int i = tid; i < 64 * 32; i += 256) {
            int r = i >> 5, d4 = (i & 31) << 2;
            *(float4*)&Vs[r * 128 + d4] =
                *(const float4*)&Vc[(((size_t)(b * QLEN) + k0 + r) * NKV + kvh) * HD + d4];
        }
        __syncthreads();

        ull accs[4][2];
#pragma unroll
        for (int i = 0; i < 4; i++) { accs[i][0] = 0ULL; accs[i][1] = 0ULL; }
#pragma unroll 4
        for (int d = 0; d < 128; d++) {
            ulonglong2 kk = *(const ulonglong2*)&Kt[d * 64 + ((tx ^ (d & 15)) << 2)];
#pragma unroll
            for (int i = 0; i < 4; i++) {
                float qv = Qs[(qy + i) * 132 + d];
                ull qq = pack2(qv, qv);
                fma2(accs[i][0], qq, kk.x);
                fma2(accs[i][1], qq, kk.y);
            }
        }

        float alpha[4];
#pragma unroll
        for (int i = 0; i < 4; i++) {
            float s0, s1, s2, s3;
            unpack2(accs[i][0], s0, s1);
            unpack2(accs[i][1], s2, s3);
            s0 *= SCALE; s1 *= SCALE; s2 *= SCALE; s3 *= SCALE;
            if (masked) {
                int iq = q0 + qy + i;
                int kend = (iq < 4) ? 4 : (iq & ~3);
                int kb = k0 + tx * 4;
                if (kb + 0 >= kend) s0 = -1e30f;
                if (kb + 1 >= kend) s1 = -1e30f;
                if (kb + 2 >= kend) s2 = -1e30f;
                if (kb + 3 >= kend) s3 = -1e30f;
            }
            float mt = fmaxf(fmaxf(s0, s1), fmaxf(s2, s3));
#pragma unroll
            for (int o = 8; o > 0; o >>= 1) mt = fmaxf(mt, __shfl_xor_sync(0xffffffffu, mt, o));
            float mn = fmaxf(m_run[i], mt);
            float al = __expf(m_run[i] - mn);
            m_run[i] = mn;
            float p0 = __expf(s0 - mn), p1 = __expf(s1 - mn);
            float p2 = __expf(s2 - mn), p3 = __expf(s3 - mn);
            float rs = p0 + p1 + p2 + p3;
#pragma unroll
            for (int o = 8; o > 0; o >>= 1) rs += __shfl_xor_sync(0xffffffffu, rs, o);
            l_run[i] = l_run[i] * al + rs;
            alpha[i] = al;
            *(float4*)&Ps[(qy + i) * 68 + tx * 4] = make_float4(p0, p1, p2, p3);
        }
#pragma unroll
        for (int i = 0; i < 4; i++) {
            ull a2 = pack2(alpha[i], alpha[i]);
#pragma unroll
            for (int jp = 0; jp < 4; jp++) mul2(acco[i][jp], acco[i][jp], a2);
        }
        __syncthreads();

#pragma unroll 4
        for (int k = 0; k < 64; k++) {
            ulonglong2 v0 = *(const ulonglong2*)&Vs[k * 128 + tx * 8];
            ulonglong2 v1 = *(const ulonglong2*)&Vs[k * 128 + tx * 8 + 4];
#pragma unroll
            for (int i = 0; i < 4; i++) {
                float pv = Ps[(qy + i) * 68 + k];
                ull pp = pack2(pv, pv);
                fma2(acco[i][0], pp, v0.x);
                fma2(acco[i][1], pp, v0.y);
                fma2(acco[i][2], pp, v1.x);
                fma2(acco[i][3], pp, v1.y);
            }
        }
    }

#pragma unroll
    for (int i = 0; i < 4; i++) {
        float inv = 1.0f / l_run[i];
        float o[8];
        unpack2(acco[i][0], o[0], o[1]);
        unpack2(acco[i][1], o[2], o[3]);
        unpack2(acco[i][2], o[4], o[5]);
        unpack2(acco[i][3], o[6], o[7]);
        size_t base = (((size_t)b * QLEN + q0 + qy + i) * NH + h) * HD + tx * 8;
        *(float4*)&g_ao[base]     = make_float4(o[0]*inv, o[1]*inv, o[2]*inv, o[3]*inv);
        *(float4*)&g_ao[base + 4] = make_float4(o[4]*inv, o[5]*inv, o[6]*inv, o[7]*inv);
    }
}

// ---------------------------------------------------------------------------
extern "C" void kernel_launch(void* const* d_in, const int* in_sizes, int n_in,
                              void* d_out, int out_size)
{
    const float* X    = (const float*)d_in[0];
    const float* Kc   = (const float*)d_in[1];
    const float* Vc   = (const float*)d_in[2];
    const float* cosp = (const float*)d_in[3];
    const float* sinp = (const float*)d_in[4];
    const float* Wq   = (const float*)d_in[5];
    const float* bq   = (const float*)d_in[6];
    const float* Wo   = (const float*)d_in[7];
    float* out = (float*)d_out;

    void* gaop;
    cudaGetSymbolAddress(&gaop, g_ao);

    // 1) Q projection (tf32 tensor cores) + bias, scattered to (b,h,q,d)
    tgemm128<1><<<dim3(HID / 128, (B_ * QLEN) / 128), 256>>>(
        X, Wq, bq, nullptr, B_ * QLEN, NH * HD, HID);

    // 2) RoPE in place
    rope_kernel<<<(B_ * NH * QLEN * 64) / 256, 256>>>(cosp, sinp);

    // 3) glide attention
    size_t smem = (size_t)ATT_SMEM_FLOATS * sizeof(float);
    cudaFuncSetAttribute(attn_kernel, cudaFuncAttributeMaxDynamicSharedMemorySize, (int)smem);
    attn_kernel<<<dim3(QLEN / 64, NH, B_), 256, smem>>>(Kc, Vc);

    // 4) output projection (tf32 tensor cores)
    tgemm128<0><<<dim3(HID / 128, (B_ * QLEN) / 128), 256>>>(
        (const float*)gaop, Wo, nullptr, out, B_ * QLEN, HID, NH * HD);
}

// round 7
// speedup vs baseline: 2.6885x; 1.9240x over previous
#include <cuda_runtime.h>

#define B_    2
#define QLEN  2048
#define HID   2048
#define NH    16
#define NKV   4
#define HD    128
#define BK    16

// Scratch (device globals are the sanctioned scratch mechanism)
__device__ float g_q [(size_t)B_ * NH * QLEN * HD];   // (b,h,q,d) 32MB
__device__ float g_ao[(size_t)B_ * QLEN * NH * HD];   // (b,q,h,d) 32MB

typedef unsigned long long ull;

// tf32 round-to-nearest (unbiased; applied once at SMEM/fragment build time)
__device__ __forceinline__ float tf32r(float x) {
    unsigned u; asm("cvt.rna.tf32.f32 %0, %1;" : "=r"(u) : "f"(x));
    return __uint_as_float(u);
}
__device__ __forceinline__ unsigned tf32u(float x) {
    unsigned u; asm("cvt.rna.tf32.f32 %0, %1;" : "=r"(u) : "f"(x));
    return u;
}
__device__ __forceinline__ float4 tf32r4(float4 v) {
    return make_float4(tf32r(v.x), tf32r(v.y), tf32r(v.z), tf32r(v.w));
}

__device__ __forceinline__ void mma_tf32(float* c, const unsigned* a, const unsigned* b) {
    asm("mma.sync.aligned.m16n8k8.row.col.f32.tf32.tf32.f32 "
        "{%0,%1,%2,%3}, {%4,%5,%6,%7}, {%8,%9}, {%0,%1,%2,%3};"
        : "+f"(c[0]), "+f"(c[1]), "+f"(c[2]), "+f"(c[3])
        : "r"(a[0]), "r"(a[1]), "r"(a[2]), "r"(a[3]), "r"(b[0]), "r"(b[1]));
}

// ---------------------------------------------------------------------------
// 128x128 tf32 tensor-core GEMM. 8 warps (2x4), warp tile 64x32 = 4x4 atoms
// of m16n8k8. BK=16, double-buffered SMEM, ONE syncthreads per k-step.
// QMODE=1: scatter into g_q as (b,h,q,d) + bias. QMODE=0: row-major C.
// ---------------------------------------------------------------------------
template <int QMODE>
__global__ void __launch_bounds__(256, 2)
tgemm128(const float* __restrict__ A, const float* __restrict__ Bm,
         const float* __restrict__ bias, float* __restrict__ C,
         int M, int N, int K)
{
    __shared__ float As[2][BK][132];   // [k][m], tf32-rounded
    __shared__ float Bs[2][BK][132];   // [k][n], tf32-rounded

    int tid = threadIdx.x;
    int w = tid >> 5, l = tid & 31;
    int wr = w >> 2, wc = w & 3;          // warp grid 2x4
    int gid = l >> 2, tg = l & 3;
    int bx = blockIdx.x, by = blockIdx.y;

    float c[4][4][4];
#pragma unroll
    for (int i = 0; i < 4; i++)
#pragma unroll
        for (int j = 0; j < 4; j++)
#pragma unroll
            for (int r = 0; r < 4; r++) c[i][j][r] = 0.f;

    int am = tid >> 1, ak = (tid & 1) * 8;   // A loader: 128 rows x 16 k
    int bk = tid >> 4, bn = (tid & 15) * 8;  // B loader: 16 k x 128 n
    const float* Ap = A + (size_t)(by * 128 + am) * K + ak;
    const float* Bp = Bm + (size_t)bk * N + bx * 128 + bn;

    float4 av0 = *(const float4*)(Ap);
    float4 av1 = *(const float4*)(Ap + 4);
    float4 bv0 = *(const float4*)(Bp);
    float4 bv1 = *(const float4*)(Bp + 4);

    // prologue store, buffer 0
    {
        As[0][ak+0][am] = tf32r(av0.x); As[0][ak+1][am] = tf32r(av0.y);
        As[0][ak+2][am] = tf32r(av0.z); As[0][ak+3][am] = tf32r(av0.w);
        As[0][ak+4][am] = tf32r(av1.x); As[0][ak+5][am] = tf32r(av1.y);
        As[0][ak+6][am] = tf32r(av1.z); As[0][ak+7][am] = tf32r(av1.w);
        *(float4*)&Bs[0][bk][bn]     = tf32r4(bv0);
        *(float4*)&Bs[0][bk][bn + 4] = tf32r4(bv1);
    }
    __syncthreads();

    int p = 0;
    for (int kt = 0; kt < K; kt += BK) {
        bool more = (kt + BK) < K;
        if (more) {
            av0 = *(const float4*)(Ap + kt + BK);
            av1 = *(const float4*)(Ap + kt + BK + 4);
            bv0 = *(const float4*)(Bp + (size_t)(kt + BK) * N);
            bv1 = *(const float4*)(Bp + (size_t)(kt + BK) * N + 4);
        }
#pragma unroll
        for (int ka = 0; ka < 2; ka++) {
            int kb = ka * 8;
            unsigned bf[4][2];
#pragma unroll
            for (int nj = 0; nj < 4; nj++) {
                int nb = wc * 32 + nj * 8 + gid;
                bf[nj][0] = __float_as_uint(Bs[p][kb + tg    ][nb]);
                bf[nj][1] = __float_as_uint(Bs[p][kb + tg + 4][nb]);
            }
#pragma unroll
            for (int mi = 0; mi < 4; mi++) {
                int mb = wr * 64 + mi * 16;
                unsigned af[4];
                af[0] = __float_as_uint(As[p][kb + tg    ][mb + gid]);
                af[1] = __float_as_uint(As[p][kb + tg    ][mb + gid + 8]);
                af[2] = __float_as_uint(As[p][kb + tg + 4][mb + gid]);
                af[3] = __float_as_uint(As[p][kb + tg + 4][mb + gid + 8]);
#pragma unroll
                for (int nj = 0; nj < 4; nj++)
                    mma_tf32(c[mi][nj], af, bf[nj]);
            }
        }
        if (more) {
            int q = p ^ 1;
            As[q][ak+0][am] = tf32r(av0.x); As[q][ak+1][am] = tf32r(av0.y);
            As[q][ak+2][am] = tf32r(av0.z); As[q][ak+3][am] = tf32r(av0.w);
            As[q][ak+4][am] = tf32r(av1.x); As[q][ak+5][am] = tf32r(av1.y);
            As[q][ak+6][am] = tf32r(av1.z); As[q][ak+7][am] = tf32r(av1.w);
            *(float4*)&Bs[q][bk][bn]     = tf32r4(bv0);
            *(float4*)&Bs[q][bk][bn + 4] = tf32r4(bv1);
            __syncthreads();
            p = q;
        }
    }

    // epilogue
#pragma unroll
    for (int mi = 0; mi < 4; mi++) {
#pragma unroll
        for (int nj = 0; nj < 4; nj++) {
            int row0 = by * 128 + wr * 64 + mi * 16 + gid;
            int col0 = bx * 128 + wc * 32 + nj * 8 + tg * 2;
            float b0 = bias ? bias[col0] : 0.f;
            float b1 = bias ? bias[col0 + 1] : 0.f;
            float2 v0 = make_float2(c[mi][nj][0] + b0, c[mi][nj][1] + b1);
            float2 v1 = make_float2(c[mi][nj][2] + b0, c[mi][nj][3] + b1);
            if (QMODE) {
                int b  = row0 >> 11, q = row0 & (QLEN - 1);
                int h  = col0 >> 7,  d = col0 & (HD - 1);
                *(float2*)&g_q[(((size_t)(b * NH + h)) * QLEN + q) * HD + d] = v0;
                int rb = (row0 + 8) >> 11, rq = (row0 + 8) & (QLEN - 1);
                *(float2*)&g_q[(((size_t)(rb * NH + h)) * QLEN + rq) * HD + d] = v1;
            } else {
                *(float2*)&C[(size_t)row0 * N + col0]       = v0;
                *(float2*)&C[(size_t)(row0 + 8) * N + col0] = v1;
            }
        }
    }
}

// ---------------------------------------------------------------------------
// RoPE in-place on g_q. One thread per (b,h,q,d<64) pair.
// ---------------------------------------------------------------------------
__global__ void rope_kernel(const float* __restrict__ cosp, const float* __restrict__ sinp)
{
    int t = blockIdx.x * blockDim.x + threadIdx.x;
    int d = t & 63;
    int q = (t >> 6) & (QLEN - 1);
    int bh = t >> 17;
    int b = bh >> 4;
    size_t base  = ((size_t)bh * QLEN + q) * HD;
    size_t cbase = ((size_t)b * QLEN + q) * HD;
    float x1 = g_q[base + d], x2 = g_q[base + d + 64];
    float c1 = cosp[cbase + d],      s1 = sinp[cbase + d];
    float c2 = cosp[cbase + d + 64], s2 = sinp[cbase + d + 64];
    g_q[base + d]      = x1 * c1 - x2 * s1;
    g_q[base + d + 64] = x2 * c2 + x1 * s2;
}

// ---------------------------------------------------------------------------
// Tensor-core glide attention. CTA = 128 threads (4 warps), 64-query tile.
// Warp w owns q rows [16w,16w+16) x full 64-key tiles -> softmax is warp-local.
// ALL MMA operands (Q, K, P, V) are tf32 ROUND-TO-NEAREST — HW truncation is
// biased and blew the error budget in R6 (1.32e-3); RN is unbiased.
// SMEM pads: Ks stride 132, Vs 136, Ps 68 — fragment LDS conflict-free.
// Heavy CTAs launched first (LPT).
// ---------------------------------------------------------------------------
#define ATT2_SMEM_BYTES ((64*132 + 64*136 + 64*68) * 4)

__global__ void __launch_bounds__(128, 2)
attn_tc(const float* __restrict__ Kc, const float* __restrict__ Vc)
{
    extern __shared__ float sm[];
    float* Ks = sm;                 // [64][132]  keys row-major, tf32-RN
    float* Vs = Ks + 64 * 132;      // [64][136]  values row-major, tf32-RN
    float* Ps = Vs + 64 * 136;      // [64][68]   probs, tf32-RN
    float* Qs = sm;                 // staging, aliases Ks (used before loop)

    const float SCALE = 0.08838834764831843f;  // 128^-0.5

    int tid = threadIdx.x;
    int w = tid >> 5, l = tid & 31;
    int gid = l >> 2, tg = l & 3;
    int qi = (gridDim.x - 1) - blockIdx.x;   // heavy tiles first
    int h = blockIdx.y, b = blockIdx.z;
    int q0 = qi * 64;
    int kvh = h >> 2;
    int qrow = w * 16;                        // warp's q base within tile

    // stage Q, build tf32-RN A fragments in registers, then release staging
    {
        const float* qg = &g_q[(((size_t)(b * NH + h)) * QLEN + q0) * HD];
        for (int i = tid; i < 64 * 32; i += 128) {
            int r = i >> 5, c4 = (i & 31) << 2;
            *(float4*)&Qs[r * 132 + c4] = *(const float4*)&qg[r * HD + c4];
        }
    }
    __syncthreads();
    unsigned qa[16][4];
#pragma unroll
    for (int ks = 0; ks < 16; ks++) {
        int col = ks * 8 + tg;
        qa[ks][0] = tf32u(Qs[(qrow + gid    ) * 132 + col]);
        qa[ks][1] = tf32u(Qs[(qrow + gid + 8) * 132 + col]);
        qa[ks][2] = tf32u(Qs[(qrow + gid    ) * 132 + col + 4]);
        qa[ks][3] = tf32u(Qs[(qrow + gid + 8) * 132 + col + 4]);
    }

    float oc[16][4];
#pragma unroll
    for (int j = 0; j < 16; j++)
#pragma unroll
        for (int r = 0; r < 4; r++) oc[j][r] = 0.f;
    float m_run[2] = {-1e30f, -1e30f};
    float l_run[2] = {0.f, 0.f};

    int ntiles = qi + 1;

    for (int t = 0; t < ntiles; t++) {
        int k0 = t * 64;
        bool masked = (t == ntiles - 1);
        __syncthreads();   // previous tile's Ks/Vs readers done (also covers Qs)

        // load K,V tiles, tf32-RN at store (row = key, d contiguous)
        for (int i = tid; i < 64 * 32; i += 128) {
            int r = i >> 5, c4 = (i & 31) << 2;
            size_t src = (((size_t)(b * QLEN) + k0 + r) * NKV + kvh) * HD + c4;
            *(float4*)&Ks[r * 132 + c4] = tf32r4(*(const float4*)&Kc[src]);
            *(float4*)&Vs[r * 136 + c4] = tf32r4(*(const float4*)&Vc[src]);
        }
        __syncthreads();

        // ---- S = Q K^T : 16 k-steps(d) x 8 n-atoms(keys) ----
        float sc[8][4];
#pragma unroll
        for (int j = 0; j < 8; j++)
#pragma unroll
            for (int r = 0; r < 4; r++) sc[j][r] = 0.f;
#pragma unroll
        for (int ks = 0; ks < 16; ks++) {
            int d0 = ks * 8 + tg;
#pragma unroll
            for (int j = 0; j < 8; j++) {
                unsigned bf[2];
                bf[0] = __float_as_uint(Ks[(j * 8 + gid) * 132 + d0]);
                bf[1] = __float_as_uint(Ks[(j * 8 + gid) * 132 + d0 + 4]);
                mma_tf32(sc[j], qa[ks], bf);
            }
        }

        // ---- warp-local online softmax (rows gid, gid+8) ----
        float alpha_h[2];
#pragma unroll
        for (int hf = 0; hf < 2; hf++) {
            int rowq = q0 + qrow + gid + hf * 8;
            int kend = masked ? ((rowq < 4) ? 4 : (rowq & ~3)) : (1 << 30);
            float mx = -1e30f;
#pragma unroll
            for (int j = 0; j < 8; j++) {
#pragma unroll
                for (int cc = 0; cc < 2; cc++) {
                    float v = sc[j][hf * 2 + cc] * SCALE;
                    int col = k0 + j * 8 + tg * 2 + cc;
                    if (col >= kend) v = -1e30f;
                    sc[j][hf * 2 + cc] = v;
                    mx = fmaxf(mx, v);
                }
            }
            mx = fmaxf(mx, __shfl_xor_sync(0xffffffffu, mx, 1));
            mx = fmaxf(mx, __shfl_xor_sync(0xffffffffu, mx, 2));
            float mn = fmaxf(m_run[hf], mx);
            float al = __expf(m_run[hf] - mn);
            m_run[hf] = mn;
            float sum = 0.f;
#pragma unroll
            for (int j = 0; j < 8; j++) {
                // round P to tf32 BEFORE summing so l_run matches the PV numerator
                float p0 = tf32r(__expf(sc[j][hf * 2]     - mn));
                float p1 = tf32r(__expf(sc[j][hf * 2 + 1] - mn));
                sum += p0 + p1;
                *(float2*)&Ps[(qrow + gid + hf * 8) * 68 + j * 8 + tg * 2] =
                    make_float2(p0, p1);
            }
            sum += __shfl_xor_sync(0xffffffffu, sum, 1);
            sum += __shfl_xor_sync(0xffffffffu, sum, 2);
            l_run[hf] = l_run[hf] * al + sum;
            alpha_h[hf] = al;
        }
        __syncwarp();   // Ps rows are warp-exclusive; order STS -> LDS in-warp

        // rescale running O
#pragma unroll
        for (int j = 0; j < 16; j++) {
            oc[j][0] *= alpha_h[0]; oc[j][1] *= alpha_h[0];
            oc[j][2] *= alpha_h[1]; oc[j][3] *= alpha_h[1];
        }

        // ---- O += P V : 8 k-steps(keys) x 16 n-atoms(d) ----
#pragma unroll
        for (int kbi = 0; kbi < 8; kbi++) {
            int kb = kbi * 8;
            unsigned af[4];
            af[0] = __float_as_uint(Ps[(qrow + gid    ) * 68 + kb + tg]);
            af[1] = __float_as_uint(Ps[(qrow + gid + 8) * 68 + kb + tg]);
            af[2] = __float_as_uint(Ps[(qrow + gid    ) * 68 + kb + tg + 4]);
            af[3] = __float_as_uint(Ps[(qrow + gid + 8) * 68 + kb + tg + 4]);
#pragma unroll
            for (int j = 0; j < 16; j++) {
                unsigned bf[2];
                bf[0] = __float_as_uint(Vs[(kb + tg    ) * 136 + j * 8 + gid]);
                bf[1] = __float_as_uint(Vs[(kb + tg + 4) * 136 + j * 8 + gid]);
                mma_tf32(oc[j], af, bf);
            }
        }
    }

    // normalize + store to (b,q,h,d)
    float inv0 = 1.0f / l_run[0];
    float inv1 = 1.0f / l_run[1];
    int row0 = q0 + qrow + gid;
#pragma unroll
    for (int j = 0; j < 16; j++) {
        int d = j * 8 + tg * 2;
        *(float2*)&g_ao[(((size_t)b * QLEN + row0) * NH + h) * HD + d] =
            make_float2(oc[j][0] * inv0, oc[j][1] * inv0);
        *(float2*)&g_ao[(((size_t)b * QLEN + row0 + 8) * NH + h) * HD + d] =
            make_float2(oc[j][2] * inv1, oc[j][3] * inv1);
    }
}

// ---------------------------------------------------------------------------
extern "C" void kernel_launch(void* const* d_in, const int* in_sizes, int n_in,
                              void* d_out, int out_size)
{
    const float* X    = (const float*)d_in[0];
    const float* Kc   = (const float*)d_in[1];
    const float* Vc   = (const float*)d_in[2];
    const float* cosp = (const float*)d_in[3];
    const float* sinp = (const float*)d_in[4];
    const float* Wq   = (const float*)d_in[5];
    const float* bq   = (const float*)d_in[6];
    const float* Wo   = (const float*)d_in[7];
    float* out = (float*)d_out;

    void* gaop;
    cudaGetSymbolAddress(&gaop, g_ao);

    // 1) Q projection (tf32 tensor cores) + bias, scattered to (b,h,q,d)
    tgemm128<1><<<dim3(HID / 128, (B_ * QLEN) / 128), 256>>>(
        X, Wq, bq, nullptr, B_ * QLEN, NH * HD, HID);

    // 2) RoPE in place
    rope_kernel<<<(B_ * NH * QLEN * 64) / 256, 256>>>(cosp, sinp);

    // 3) glide attention (tensor cores, tf32-RN operands)
    cudaFuncSetAttribute(attn_tc, cudaFuncAttributeMaxDynamicSharedMemorySize,
                         ATT2_SMEM_BYTES);
    attn_tc<<<dim3(QLEN / 64, NH, B_), 128, ATT2_SMEM_BYTES>>>(Kc, Vc);

    // 4) output projection (tf32 tensor cores)
    tgemm128<0><<<dim3(HID / 128, (B_ * QLEN) / 128), 256>>>(
        (const float*)gaop, Wo, nullptr, out, B_ * QLEN, HID, NH * HD);
}

// round 8
// speedup vs baseline: 3.0750x; 1.1437x over previous
#include <cuda_runtime.h>

#define B_    2
#define QLEN  2048
#define HID   2048
#define NH    16
#define NKV   4
#define HD    128
#define BK    16

// Scratch (device globals are the sanctioned scratch mechanism)
__device__ float g_q [(size_t)B_ * NH * QLEN * HD];   // (b,h,q,d) 32MB
__device__ float g_ao[(size_t)B_ * QLEN * NH * HD];   // (b,q,h,d) 32MB

typedef unsigned long long ull;

// tf32 round-to-nearest (unbiased; applied once at SMEM/fragment build time)
__device__ __forceinline__ float tf32r(float x) {
    unsigned u; asm("cvt.rna.tf32.f32 %0, %1;" : "=r"(u) : "f"(x));
    return __uint_as_float(u);
}
__device__ __forceinline__ unsigned tf32u(float x) {
    unsigned u; asm("cvt.rna.tf32.f32 %0, %1;" : "=r"(u) : "f"(x));
    return u;
}
__device__ __forceinline__ float4 tf32r4(float4 v) {
    return make_float4(tf32r(v.x), tf32r(v.y), tf32r(v.z), tf32r(v.w));
}

__device__ __forceinline__ void mma_tf32(float* c, const unsigned* a, const unsigned* b) {
    asm("mma.sync.aligned.m16n8k8.row.col.f32.tf32.tf32.f32 "
        "{%0,%1,%2,%3}, {%4,%5,%6,%7}, {%8,%9}, {%0,%1,%2,%3};"
        : "+f"(c[0]), "+f"(c[1]), "+f"(c[2]), "+f"(c[3])
        : "r"(a[0]), "r"(a[1]), "r"(a[2]), "r"(a[3]), "r"(b[0]), "r"(b[1]));
}

// ---------------------------------------------------------------------------
// 128x128 tf32 tensor-core GEMM. 8 warps (2x4), warp tile 64x32 = 4x4 atoms
// of m16n8k8. BK=16, double-buffered SMEM, ONE syncthreads per k-step.
// Row stride 136: fragment-load bank = 8*tg + gid — bijection over all 32
// banks (stride 132 had 2-way conflicts: bank 4*tg+gid covers only 20 banks).
// QMODE=1: scatter into g_q as (b,h,q,d) + bias. QMODE=0: row-major C.
// ---------------------------------------------------------------------------
#define GSTR 136

template <int QMODE>
__global__ void __launch_bounds__(256, 2)
tgemm128(const float* __restrict__ A, const float* __restrict__ Bm,
         const float* __restrict__ bias, float* __restrict__ C,
         int M, int N, int K)
{
    __shared__ float As[2][BK][GSTR];   // [k][m], tf32-rounded
    __shared__ float Bs[2][BK][GSTR];   // [k][n], tf32-rounded

    int tid = threadIdx.x;
    int w = tid >> 5, l = tid & 31;
    int wr = w >> 2, wc = w & 3;          // warp grid 2x4
    int gid = l >> 2, tg = l & 3;
    int bx = blockIdx.x, by = blockIdx.y;

    float c[4][4][4];
#pragma unroll
    for (int i = 0; i < 4; i++)
#pragma unroll
        for (int j = 0; j < 4; j++)
#pragma unroll
            for (int r = 0; r < 4; r++) c[i][j][r] = 0.f;

    int am = tid >> 1, ak = (tid & 1) * 8;   // A loader: 128 rows x 16 k
    int bk = tid >> 4, bn = (tid & 15) * 8;  // B loader: 16 k x 128 n
    const float* Ap = A + (size_t)(by * 128 + am) * K + ak;
    const float* Bp = Bm + (size_t)bk * N + bx * 128 + bn;

    float4 av0 = *(const float4*)(Ap);
    float4 av1 = *(const float4*)(Ap + 4);
    float4 bv0 = *(const float4*)(Bp);
    float4 bv1 = *(const float4*)(Bp + 4);

    // prologue store, buffer 0
    {
        As[0][ak+0][am] = tf32r(av0.x); As[0][ak+1][am] = tf32r(av0.y);
        As[0][ak+2][am] = tf32r(av0.z); As[0][ak+3][am] = tf32r(av0.w);
        As[0][ak+4][am] = tf32r(av1.x); As[0][ak+5][am] = tf32r(av1.y);
        As[0][ak+6][am] = tf32r(av1.z); As[0][ak+7][am] = tf32r(av1.w);
        *(float4*)&Bs[0][bk][bn]     = tf32r4(bv0);
        *(float4*)&Bs[0][bk][bn + 4] = tf32r4(bv1);
    }
    __syncthreads();

    int p = 0;
    for (int kt = 0; kt < K; kt += BK) {
        bool more = (kt + BK) < K;
        if (more) {
            av0 = *(const float4*)(Ap + kt + BK);
            av1 = *(const float4*)(Ap + kt + BK + 4);
            bv0 = *(const float4*)(Bp + (size_t)(kt + BK) * N);
            bv1 = *(const float4*)(Bp + (size_t)(kt + BK) * N + 4);
        }
#pragma unroll
        for (int ka = 0; ka < 2; ka++) {
            int kb = ka * 8;
            unsigned bf[4][2];
#pragma unroll
            for (int nj = 0; nj < 4; nj++) {
                int nb = wc * 32 + nj * 8 + gid;
                bf[nj][0] = __float_as_uint(Bs[p][kb + tg    ][nb]);
                bf[nj][1] = __float_as_uint(Bs[p][kb + tg + 4][nb]);
            }
#pragma unroll
            for (int mi = 0; mi < 4; mi++) {
                int mb = wr * 64 + mi * 16;
                unsigned af[4];
                af[0] = __float_as_uint(As[p][kb + tg    ][mb + gid]);
                af[1] = __float_as_uint(As[p][kb + tg    ][mb + gid + 8]);
                af[2] = __float_as_uint(As[p][kb + tg + 4][mb + gid]);
                af[3] = __float_as_uint(As[p][kb + tg + 4][mb + gid + 8]);
#pragma unroll
                for (int nj = 0; nj < 4; nj++)
                    mma_tf32(c[mi][nj], af, bf[nj]);
            }
        }
        if (more) {
            int q = p ^ 1;
            As[q][ak+0][am] = tf32r(av0.x); As[q][ak+1][am] = tf32r(av0.y);
            As[q][ak+2][am] = tf32r(av0.z); As[q][ak+3][am] = tf32r(av0.w);
            As[q][ak+4][am] = tf32r(av1.x); As[q][ak+5][am] = tf32r(av1.y);
            As[q][ak+6][am] = tf32r(av1.z); As[q][ak+7][am] = tf32r(av1.w);
            *(float4*)&Bs[q][bk][bn]     = tf32r4(bv0);
            *(float4*)&Bs[q][bk][bn + 4] = tf32r4(bv1);
            __syncthreads();
            p = q;
        }
    }

    // epilogue
#pragma unroll
    for (int mi = 0; mi < 4; mi++) {
#pragma unroll
        for (int nj = 0; nj < 4; nj++) {
            int row0 = by * 128 + wr * 64 + mi * 16 + gid;
            int col0 = bx * 128 + wc * 32 + nj * 8 + tg * 2;
            float b0 = bias ? bias[col0] : 0.f;
            float b1 = bias ? bias[col0 + 1] : 0.f;
            float2 v0 = make_float2(c[mi][nj][0] + b0, c[mi][nj][1] + b1);
            float2 v1 = make_float2(c[mi][nj][2] + b0, c[mi][nj][3] + b1);
            if (QMODE) {
                int b  = row0 >> 11, q = row0 & (QLEN - 1);
                int h  = col0 >> 7,  d = col0 & (HD - 1);
                *(float2*)&g_q[(((size_t)(b * NH + h)) * QLEN + q) * HD + d] = v0;
                int rb = (row0 + 8) >> 11, rq = (row0 + 8) & (QLEN - 1);
                *(float2*)&g_q[(((size_t)(rb * NH + h)) * QLEN + rq) * HD + d] = v1;
            } else {
                *(float2*)&C[(size_t)row0 * N + col0]       = v0;
                *(float2*)&C[(size_t)(row0 + 8) * N + col0] = v1;
            }
        }
    }
}

// ---------------------------------------------------------------------------
// RoPE in-place on g_q. One thread per (b,h,q,d<64) pair.
// ---------------------------------------------------------------------------
__global__ void rope_kernel(const float* __restrict__ cosp, const float* __restrict__ sinp)
{
    int t = blockIdx.x * blockDim.x + threadIdx.x;
    int d = t & 63;
    int q = (t >> 6) & (QLEN - 1);
    int bh = t >> 17;
    int b = bh >> 4;
    size_t base  = ((size_t)bh * QLEN + q) * HD;
    size_t cbase = ((size_t)b * QLEN + q) * HD;
    float x1 = g_q[base + d], x2 = g_q[base + d + 64];
    float c1 = cosp[cbase + d],      s1 = sinp[cbase + d];
    float c2 = cosp[cbase + d + 64], s2 = sinp[cbase + d + 64];
    g_q[base + d]      = x1 * c1 - x2 * s1;
    g_q[base + d + 64] = x2 * c2 + x1 * s2;
}

// ---------------------------------------------------------------------------
// Tensor-core glide attention. CTA = 128 threads (4 warps), 64-query tile.
// Warp w owns q rows [16w,16w+16) x full 64-key tiles -> softmax is warp-local.
// ALL MMA operands (Q, K, P, V) are tf32 ROUND-TO-NEAREST (unbiased).
// SMEM pads: Ks stride 132, Vs 136, Ps 68 — fragment LDS conflict-free.
// Heavy CTAs launched first (LPT).
// ---------------------------------------------------------------------------
#define ATT2_SMEM_BYTES ((64*132 + 64*136 + 64*68) * 4)

__global__ void __launch_bounds__(128, 2)
attn_tc(const float* __restrict__ Kc, const float* __restrict__ Vc)
{
    extern __shared__ float sm[];
    float* Ks = sm;                 // [64][132]  keys row-major, tf32-RN
    float* Vs = Ks + 64 * 132;      // [64][136]  values row-major, tf32-RN
    float* Ps = Vs + 64 * 136;      // [64][68]   probs, tf32-RN
    float* Qs = sm;                 // staging, aliases Ks (used before loop)

    const float SCALE = 0.08838834764831843f;  // 128^-0.5

    int tid = threadIdx.x;
    int w = tid >> 5, l = tid & 31;
    int gid = l >> 2, tg = l & 3;
    int qi = (gridDim.x - 1) - blockIdx.x;   // heavy tiles first
    int h = blockIdx.y, b = blockIdx.z;
    int q0 = qi * 64;
    int kvh = h >> 2;
    int qrow = w * 16;                        // warp's q base within tile

    // stage Q, build tf32-RN A fragments in registers, then release staging
    {
        const float* qg = &g_q[(((size_t)(b * NH + h)) * QLEN + q0) * HD];
        for (int i = tid; i < 64 * 32; i += 128) {
            int r = i >> 5, c4 = (i & 31) << 2;
            *(float4*)&Qs[r * 132 + c4] = *(const float4*)&qg[r * HD + c4];
        }
    }
    __syncthreads();
    unsigned qa[16][4];
#pragma unroll
    for (int ks = 0; ks < 16; ks++) {
        int col = ks * 8 + tg;
        qa[ks][0] = tf32u(Qs[(qrow + gid    ) * 132 + col]);
        qa[ks][1] = tf32u(Qs[(qrow + gid + 8) * 132 + col]);
        qa[ks][2] = tf32u(Qs[(qrow + gid    ) * 132 + col + 4]);
        qa[ks][3] = tf32u(Qs[(qrow + gid + 8) * 132 + col + 4]);
    }

    float oc[16][4];
#pragma unroll
    for (int j = 0; j < 16; j++)
#pragma unroll
        for (int r = 0; r < 4; r++) oc[j][r] = 0.f;
    float m_run[2] = {-1e30f, -1e30f};
    float l_run[2] = {0.f, 0.f};

    int ntiles = qi + 1;

    for (int t = 0; t < ntiles; t++) {
        int k0 = t * 64;
        bool masked = (t == ntiles - 1);
        __syncthreads();   // previous tile's Ks/Vs readers done (also covers Qs)

        // load K,V tiles, tf32-RN at store (row = key, d contiguous)
        for (int i = tid; i < 64 * 32; i += 128) {
            int r = i >> 5, c4 = (i & 31) << 2;
            size_t src = (((size_t)(b * QLEN) + k0 + r) * NKV + kvh) * HD + c4;
            *(float4*)&Ks[r * 132 + c4] = tf32r4(*(const float4*)&Kc[src]);
            *(float4*)&Vs[r * 136 + c4] = tf32r4(*(const float4*)&Vc[src]);
        }
        __syncthreads();

        // ---- S = Q K^T : 16 k-steps(d) x 8 n-atoms(keys) ----
        float sc[8][4];
#pragma unroll
        for (int j = 0; j < 8; j++)
#pragma unroll
            for (int r = 0; r < 4; r++) sc[j][r] = 0.f;
#pragma unroll
        for (int ks = 0; ks < 16; ks++) {
            int d0 = ks * 8 + tg;
#pragma unroll
            for (int j = 0; j < 8; j++) {
                unsigned bf[2];
                bf[0] = __float_as_uint(Ks[(j * 8 + gid) * 132 + d0]);
                bf[1] = __float_as_uint(Ks[(j * 8 + gid) * 132 + d0 + 4]);
                mma_tf32(sc[j], qa[ks], bf);
            }
        }

        // ---- warp-local online softmax (rows gid, gid+8) ----
        float alpha_h[2];
#pragma unroll
        for (int hf = 0; hf < 2; hf++) {
            int rowq = q0 + qrow + gid + hf * 8;
            int kend = masked ? ((rowq < 4) ? 4 : (rowq & ~3)) : (1 << 30);
            float mx = -1e30f;
#pragma unroll
            for (int j = 0; j < 8; j++) {
#pragma unroll
                for (int cc = 0; cc < 2; cc++) {
                    float v = sc[j][hf * 2 + cc] * SCALE;
                    int col = k0 + j * 8 + tg * 2 + cc;
                    if (col >= kend) v = -1e30f;
                    sc[j][hf * 2 + cc] = v;
                    mx = fmaxf(mx, v);
                }
            }
            mx = fmaxf(mx, __shfl_xor_sync(0xffffffffu, mx, 1));
            mx = fmaxf(mx, __shfl_xor_sync(0xffffffffu, mx, 2));
            float mn = fmaxf(m_run[hf], mx);
            float al = __expf(m_run[hf] - mn);
            m_run[hf] = mn;
            float sum = 0.f;
#pragma unroll
            for (int j = 0; j < 8; j++) {
                // round P to tf32 BEFORE summing so l_run matches the PV numerator
                float p0 = tf32r(__expf(sc[j][hf * 2]     - mn));
                float p1 = tf32r(__expf(sc[j][hf * 2 + 1] - mn));
                sum += p0 + p1;
                *(float2*)&Ps[(qrow + gid + hf * 8) * 68 + j * 8 + tg * 2] =
                    make_float2(p0, p1);
            }
            sum += __shfl_xor_sync(0xffffffffu, sum, 1);
            sum += __shfl_xor_sync(0xffffffffu, sum, 2);
            l_run[hf] = l_run[hf] * al + sum;
            alpha_h[hf] = al;
        }
        __syncwarp();   // Ps rows are warp-exclusive; order STS -> LDS in-warp

        // rescale running O
#pragma unroll
        for (int j = 0; j < 16; j++) {
            oc[j][0] *= alpha_h[0]; oc[j][1] *= alpha_h[0];
            oc[j][2] *= alpha_h[1]; oc[j][3] *= alpha_h[1];
        }

        // ---- O += P V : 8 k-steps(keys) x 16 n-atoms(d) ----
#pragma unroll
        for (int kbi = 0; kbi < 8; kbi++) {
            int kb = kbi * 8;
            unsigned af[4];
            af[0] = __float_as_uint(Ps[(qrow + gid    ) * 68 + kb + tg]);
            af[1] = __float_as_uint(Ps[(qrow + gid + 8) * 68 + kb + tg]);
            af[2] = __float_as_uint(Ps[(qrow + gid    ) * 68 + kb + tg + 4]);
            af[3] = __float_as_uint(Ps[(qrow + gid + 8) * 68 + kb + tg + 4]);
#pragma unroll
            for (int j = 0; j < 16; j++) {
                unsigned bf[2];
                bf[0] = __float_as_uint(Vs[(kb + tg    ) * 136 + j * 8 + gid]);
                bf[1] = __float_as_uint(Vs[(kb + tg + 4) * 136 + j * 8 + gid]);
                mma_tf32(oc[j], af, bf);
            }
        }
    }

    // normalize + store to (b,q,h,d)
    float inv0 = 1.0f / l_run[0];
    float inv1 = 1.0f / l_run[1];
    int row0 = q0 + qrow + gid;
#pragma unroll
    for (int j = 0; j < 16; j++) {
        int d = j * 8 + tg * 2;
        *(float2*)&g_ao[(((size_t)b * QLEN + row0) * NH + h) * HD + d] =
            make_float2(oc[j][0] * inv0, oc[j][1] * inv0);
        *(float2*)&g_ao[(((size_t)b * QLEN + row0 + 8) * NH + h) * HD + d] =
            make_float2(oc[j][2] * inv1, oc[j][3] * inv1);
    }
}

// ---------------------------------------------------------------------------
extern "C" void kernel_launch(void* const* d_in, const int* in_sizes, int n_in,
                              void* d_out, int out_size)
{
    const float* X    = (const float*)d_in[0];
    const float* Kc   = (const float*)d_in[1];
    const float* Vc   = (const float*)d_in[2];
    const float* cosp = (const float*)d_in[3];
    const float* sinp = (const float*)d_in[4];
    const float* Wq   = (const float*)d_in[5];
    const float* bq   = (const float*)d_in[6];
    const float* Wo   = (const float*)d_in[7];
    float* out = (float*)d_out;

    void* gaop;
    cudaGetSymbolAddress(&gaop, g_ao);

    // 1) Q projection (tf32 tensor cores) + bias, scattered to (b,h,q,d)
    tgemm128<1><<<dim3(HID / 128, (B_ * QLEN) / 128), 256>>>(
        X, Wq, bq, nullptr, B_ * QLEN, NH * HD, HID);

    // 2) RoPE in place
    rope_kernel<<<(B_ * NH * QLEN * 64) / 256, 256>>>(cosp, sinp);

    // 3) glide attention (tensor cores, tf32-RN operands)
    cudaFuncSetAttribute(attn_tc, cudaFuncAttributeMaxDynamicSharedMemorySize,
                         ATT2_SMEM_BYTES);
    attn_tc<<<dim3(QLEN / 64, NH, B_), 128, ATT2_SMEM_BYTES>>>(Kc, Vc);

    // 4) output projection (tf32 tensor cores)
    tgemm128<0><<<dim3(HID / 128, (B_ * QLEN) / 128), 256>>>(
        (const float*)gaop, Wo, nullptr, out, B_ * QLEN, HID, NH * HD);
}